// round 2
// baseline (speedup 1.0000x reference)
#include <cuda_runtime.h>
#include <cuda_bf16.h>

// ---------------------------------------------------------------------------
// Self_Attention (softmax discarded in reference => pure linear chain):
//   out_b = (1/sqrt(D)) * X_b * (Wq^T Wk) * (X_b^T X_b) * Wv^T
// Computed as:
//   A   = Wq^T * Wk                 [D,D]      (once)
//   G_b = X_b^T * X_b               [D,D]      (per batch)
//   T_b = A * G_b                   [D,D]
//   M_b = (1/32) * T_b * Wv^T       [D,D]
//   out_b = X_b * M_b               [S,D]
// D=1024, S=2048, B=4. ~54 GFLOP total vs 189 GFLOP direct; no SxS tensor.
// ---------------------------------------------------------------------------

#define B_ 4
#define S_ 2048
#define D_ 1024

// Scratch (allocation-free rule: __device__ globals)
__device__ float g_A[D_ * D_];        //  4 MB
__device__ float g_G[B_ * D_ * D_];   // 16 MB
__device__ float g_T[B_ * D_ * D_];   // 16 MB
__device__ float g_M[B_ * D_ * D_];   // 16 MB

// SIMT fp32 GEMM, 128x128x8 tile, 8x8 per thread, double-buffered smem
// (one __syncthreads per K-tile; next tile's global loads overlap compute).
// op(A)[m,k] = TA ? A[k*lda+m] : A[m*lda+k]
// op(B)[k,n] = TB ? B[n*ldb+k] : B[k*ldb+n]
// Dims: M,N multiples of 128; K multiple of 8 -> no bounds checks.
template <bool TA, bool TB>
__global__ __launch_bounds__(256, 2)
void gemm128(const float* __restrict__ Ag, const float* __restrict__ Bg,
             float* __restrict__ Cg,
             int M, int N, int K, int lda, int ldb, int ldc,
             long sA, long sB, long sC, float alpha)
{
    constexpr int BM = 128, BN = 128, BK = 8, TM = 8, TN = 8;

    __shared__ float As[2][BK][BM];
    __shared__ float Bs[2][BK][BN];

    const float* A = Ag + (long)blockIdx.z * sA;
    const float* B = Bg + (long)blockIdx.z * sB;
    float*       C = Cg + (long)blockIdx.z * sC;

    const int m0 = blockIdx.y * BM;
    const int n0 = blockIdx.x * BN;
    const int tid = threadIdx.x;          // 256 threads
    const int tx = tid % 16;              // 16x16 thread grid, 8x8 per thread
    const int ty = tid / 16;

    float acc[TM][TN];
    #pragma unroll
    for (int i = 0; i < TM; ++i)
        #pragma unroll
        for (int j = 0; j < TN; ++j)
            acc[i][j] = 0.0f;

    // ---- tile loaders (global -> smem buffer `b`) ----
    auto loadA = [&](int k0, int b) {
        #pragma unroll
        for (int i = 0; i < (BM * BK) / 256; ++i) {
            int idx = tid + i * 256;
            if (TA) {
                int k = idx / BM, m = idx % BM;            // coalesced along m
                As[b][k][m] = A[(long)(k0 + k) * lda + (m0 + m)];
            } else {
                int m = idx / BK, k = idx % BK;            // 32B-sector coalesced
                As[b][k][m] = A[(long)(m0 + m) * lda + (k0 + k)];
            }
        }
    };
    auto loadB = [&](int k0, int b) {
        #pragma unroll
        for (int i = 0; i < (BN * BK) / 256; ++i) {
            int idx = tid + i * 256;
            if (!TB) {
                int k = idx / BN, n = idx % BN;            // coalesced along n
                Bs[b][k][n] = B[(long)(k0 + k) * ldb + (n0 + n)];
            } else {
                int n = idx / BK, k = idx % BK;            // 32B-sector coalesced
                Bs[b][k][n] = B[(long)(n0 + n) * ldb + (k0 + k)];
            }
        }
    };

    int buf = 0;
    loadA(0, buf);
    loadB(0, buf);
    __syncthreads();

    for (int k0 = 0; k0 < K; k0 += BK) {
        const int nxt = buf ^ 1;
        if (k0 + BK < K) {              // prefetch next tile while computing
            loadA(k0 + BK, nxt);
            loadB(k0 + BK, nxt);
        }

        #pragma unroll
        for (int k = 0; k < BK; ++k) {
            float ra[TM], rb[TN];
            *reinterpret_cast<float4*>(&ra[0]) = *reinterpret_cast<const float4*>(&As[buf][k][ty * TM]);
            *reinterpret_cast<float4*>(&ra[4]) = *reinterpret_cast<const float4*>(&As[buf][k][ty * TM + 4]);
            *reinterpret_cast<float4*>(&rb[0]) = *reinterpret_cast<const float4*>(&Bs[buf][k][tx * TN]);
            *reinterpret_cast<float4*>(&rb[4]) = *reinterpret_cast<const float4*>(&Bs[buf][k][tx * TN + 4]);
            #pragma unroll
            for (int i = 0; i < TM; ++i)
                #pragma unroll
                for (int j = 0; j < TN; ++j)
                    acc[i][j] += ra[i] * rb[j];
        }
        __syncthreads();                // one barrier per tile: loads of `nxt`
        buf = nxt;                      // done + reads of `buf` done
    }

    // ---- epilogue ----
    #pragma unroll
    for (int i = 0; i < TM; ++i) {
        float* crow = C + (long)(m0 + ty * TM + i) * ldc + n0 + tx * TN;
        #pragma unroll
        for (int j = 0; j < TN; j += 4) {
            float4 v;
            v.x = alpha * acc[i][j + 0];
            v.y = alpha * acc[i][j + 1];
            v.z = alpha * acc[i][j + 2];
            v.w = alpha * acc[i][j + 3];
            *reinterpret_cast<float4*>(crow + j) = v;
        }
    }
}

extern "C" void kernel_launch(void* const* d_in, const int* in_sizes, int n_in,
                              void* d_out, int out_size)
{
    const float* x  = (const float*)d_in[0];   // [4, 2048, 1024]
    const float* Wq = (const float*)d_in[1];   // [1024, 1024]
    const float* Wk = (const float*)d_in[2];
    const float* Wv = (const float*)d_in[3];
    float* out = (float*)d_out;                // [4, 2048, 1024]

    float* A = nullptr; float* G = nullptr; float* T = nullptr; float* Mb = nullptr;
    cudaGetSymbolAddress((void**)&A,  g_A);
    cudaGetSymbolAddress((void**)&G,  g_G);
    cudaGetSymbolAddress((void**)&T,  g_T);
    cudaGetSymbolAddress((void**)&Mb, g_M);

    const long DD = (long)D_ * D_;
    const long SD = (long)S_ * D_;
    const float scale = 1.0f / 32.0f;  // 1/sqrt(1024)

    dim3 blk(256);

    // 1) A = Wq^T * Wk          (TN)  M=N=K=1024
    gemm128<true, false><<<dim3(D_ / 128, D_ / 128, 1), blk>>>(
        Wq, Wk, A, D_, D_, D_, D_, D_, D_, 0, 0, 0, 1.0f);

    // 2) G_b = X_b^T * X_b      (TN)  M=N=1024, K=2048, batched
    gemm128<true, false><<<dim3(D_ / 128, D_ / 128, B_), blk>>>(
        x, x, G, D_, D_, S_, D_, D_, D_, SD, SD, DD, 1.0f);

    // 3) T_b = A * G_b          (NN)  M=N=K=1024, batched (A shared)
    gemm128<false, false><<<dim3(D_ / 128, D_ / 128, B_), blk>>>(
        A, G, T, D_, D_, D_, D_, D_, D_, 0, DD, DD, 1.0f);

    // 4) M_b = scale * T_b * Wv^T  (NT)  M=N=K=1024, batched (Wv shared)
    gemm128<false, true><<<dim3(D_ / 128, D_ / 128, B_), blk>>>(
        T, Wv, Mb, D_, D_, D_, D_, D_, D_, DD, 0, DD, scale);

    // 5) out_b = X_b * M_b      (NN)  M=2048, N=1024, K=1024, batched
    gemm128<false, false><<<dim3(D_ / 128, S_ / 128, B_), blk>>>(
        x, Mb, out, S_, D_, D_, D_, D_, D_, SD, DD, SD, 1.0f);
}